// round 3
// baseline (speedup 1.0000x reference)
#include <cuda_runtime.h>

#define BB      8
#define NN      4096
#define CC      64
#define KD      32
#define KOUT    16
#define QT      128
#define CT      64
#define NTHREADS 256

// smem floats: qT 8192 | cT 4096 | dist 8192 | sqc 64 | sqQv 128  = 20672 f
// then topk 128*32 u64
#define SMEM_BYTES ((8192 + 4096 + 8192 + 64 + 128) * 4 + QT * KD * 8)  // 115456

__device__ __forceinline__ void fma2(unsigned long long& d,
                                     unsigned long long a,
                                     unsigned long long b) {
    asm("fma.rn.f32x2 %0, %1, %2, %0;" : "+l"(d) : "l"(a), "l"(b));
}
__device__ __forceinline__ unsigned long long fma2g(unsigned long long a,
                                                    unsigned long long b,
                                                    unsigned long long c) {
    unsigned long long d;
    asm("fma.rn.f32x2 %0, %1, %2, %3;" : "=l"(d) : "l"(a), "l"(b), "l"(c));
    return d;
}
__device__ __forceinline__ unsigned long long add2(unsigned long long a,
                                                   unsigned long long b) {
    unsigned long long d;
    asm("add.rn.f32x2 %0, %1, %2;" : "=l"(d) : "l"(a), "l"(b));
    return d;
}
__device__ __forceinline__ unsigned long long pack2(float x) {
    unsigned long long r;
    asm("mov.b64 %0, {%1, %1};" : "=l"(r) : "f"(x));
    return r;
}
// order-preserving float<->uint maps (signed-compare semantics)
__device__ __forceinline__ unsigned int ord32(float f) {
    unsigned int b = __float_as_uint(f);
    return b ^ ((b & 0x80000000u) ? 0xFFFFFFFFu : 0x80000000u);
}
__device__ __forceinline__ float iord32(unsigned int y) {
    unsigned int b = (y & 0x80000000u) ? (y ^ 0x80000000u) : ~y;
    return __uint_as_float(b);
}

__global__ void __launch_bounds__(NTHREADS, 2)
knn_pe_kernel(const float* __restrict__ xyz,   // [B,N,3]
              const float* __restrict__ pts,   // [B,N,64]
              float* __restrict__ out)         // [B,N,16,10]
{
    extern __shared__ float smem[];
    float* qT   = smem;                  // 64*128 (k-major)
    float* cT   = qT + 64 * QT;          // 64*64  (k-major, f4-swizzled)
    float* dist = cT + 64 * CT;          // adj values, c-major, f2-swizzled
    float* sqc  = dist + 64 * QT;        // 64
    float* sqQv = sqc + 64;              // 128
    unsigned long long* topk = (unsigned long long*)(sqQv + QT);

    const int tid   = threadIdx.x;
    const int b     = blockIdx.y;
    const int qbase = blockIdx.x * QT;
    const float* ptsB = pts + (size_t)b * NN * CC;

    // ---- load query tile transposed (k-major)
    {
        const float4* g = (const float4*)(ptsB + (size_t)qbase * CC);
        for (int f = tid; f < QT * (CC / 4); f += NTHREADS) {
            int row = f >> 4;
            int k4  = (f & 15) << 2;
            float4 v = g[f];
            qT[(k4 + 0) * QT + row] = v.x;
            qT[(k4 + 1) * QT + row] = v.y;
            qT[(k4 + 2) * QT + row] = v.z;
            qT[(k4 + 3) * QT + row] = v.w;
        }
    }
    for (int i = tid; i < QT * KD; i += NTHREADS)
        topk[i] = 0xFFFFFFFFFFFFFFFFull;
    __syncthreads();

    // ---- sqQ (XLA-style x2-vectorized tree), staged to smem
    if (tid < QT) {
        float a[32];
        #pragma unroll
        for (int l = 0; l < 32; ++l) {
            float x0 = qT[(2 * l) * QT + tid];
            float x1 = qT[(2 * l + 1) * QT + tid];
            a[l] = __fadd_rn(__fmul_rn(x0, x0), __fmul_rn(x1, x1));
        }
        #pragma unroll
        for (int off = 16; off >= 1; off >>= 1)
            #pragma unroll
            for (int l = 0; l < 16; ++l)
                if (l < off) a[l] = __fadd_rn(a[l], a[l + off]);
        sqQv[tid] = a[0];
    }
    // ---- sqc(chunk 0) from global (same tree)
    if (tid >= 128 && tid < 128 + CT) {
        const float4* g4 = (const float4*)(ptsB + (size_t)(tid - 128) * CC);
        float a[32];
        #pragma unroll
        for (int i = 0; i < 16; ++i) {
            float4 v = g4[i];
            a[2 * i]     = __fadd_rn(__fmul_rn(v.x, v.x), __fmul_rn(v.y, v.y));
            a[2 * i + 1] = __fadd_rn(__fmul_rn(v.z, v.z), __fmul_rn(v.w, v.w));
        }
        #pragma unroll
        for (int off = 16; off >= 1; off >>= 1)
            #pragma unroll
            for (int l = 0; l < 16; ++l)
                if (l < off) a[l] = __fadd_rn(a[l], a[l + off]);
        sqc[tid - 128] = a[0];
    }

    // prefetch chunk 0 and stage into cT
    float4 pf[4];
    {
        const float4* g = (const float4*)ptsB;
        #pragma unroll
        for (int it = 0; it < 4; ++it) pf[it] = g[it * NTHREADS + tid];
    }
    __syncthreads();   // sqQv / sqc(0) ready
    #pragma unroll
    for (int it = 0; it < 4; ++it) {
        int f    = it * NTHREADS + tid;
        int c    = f >> 4;
        int k4g  = f & 15;
        int phys = (c >> 2) ^ k4g;
        int base = (k4g << 2) * CT + (phys << 2) + (c & 3);
        cT[base + 0 * CT] = pf[it].x;
        cT[base + 1 * CT] = pf[it].y;
        cT[base + 2 * CT] = pf[it].z;
        cT[base + 3 * CT] = pf[it].w;
    }
    __syncthreads();   // cT(0) ready

    const int qg = tid >> 4;
    const int cg = tid & 15;

    // per-thread query-pair norms (constant all chunks)
    unsigned long long sqp[4];
    #pragma unroll
    for (int i = 0; i < 4; ++i)
        sqp[i] = *(const unsigned long long*)(sqQv + (qg << 3) + 2 * i);
    const unsigned long long neg2 = pack2(-2.0f);

    float thr = iord32(0xFFFFFFFFu);   // NaN sentinel: slow path until row fills

    for (int chunk = 0; chunk < NN / CT; ++chunk) {
        const int cbase = chunk * CT;

        // issue global prefetch for next chunk first (hidden under GEMM)
        if (chunk + 1 < NN / CT) {
            const float4* g = (const float4*)(ptsB + (size_t)(cbase + CT) * CC);
            #pragma unroll
            for (int it = 0; it < 4; ++it) pf[it] = g[it * NTHREADS + tid];
        }

        // ---- GEMM: 8q x 4c per thread, f32x2 query pairs, ascending-k chain
        unsigned long long acc[4][4];
        #pragma unroll
        for (int i = 0; i < 4; ++i)
            #pragma unroll
            for (int j = 0; j < 4; ++j) acc[i][j] = 0ull;

        #pragma unroll 8
        for (int k = 0; k < CC; ++k) {
            const float* qrow = qT + k * QT + (qg << 3);
            ulonglong2 aa = *(const ulonglong2*)(qrow);
            ulonglong2 ab = *(const ulonglong2*)(qrow + 4);
            int phys = cg ^ ((k >> 2) & 15);
            float4 bv = *(const float4*)(cT + k * CT + (phys << 2));
            unsigned long long b0 = pack2(bv.x);
            unsigned long long b1 = pack2(bv.y);
            unsigned long long b2 = pack2(bv.z);
            unsigned long long b3 = pack2(bv.w);
            fma2(acc[0][0], aa.x, b0); fma2(acc[0][1], aa.x, b1);
            fma2(acc[0][2], aa.x, b2); fma2(acc[0][3], aa.x, b3);
            fma2(acc[1][0], aa.y, b0); fma2(acc[1][1], aa.y, b1);
            fma2(acc[1][2], aa.y, b2); fma2(acc[1][3], aa.y, b3);
            fma2(acc[2][0], ab.x, b0); fma2(acc[2][1], ab.x, b1);
            fma2(acc[2][2], ab.x, b2); fma2(acc[2][3], ab.x, b3);
            fma2(acc[3][0], ab.y, b0); fma2(acc[3][1], ab.y, b1);
            fma2(acc[3][2], ab.y, b2); fma2(acc[3][3], ab.y, b3);
        }

        // epilogue: adj = fmaf(-2, inner, sqQ) + sqc  (per-lane identical to R2)
        #pragma unroll
        for (int j = 0; j < 4; ++j) {
            int c = (cg << 2) + j;
            unsigned long long scp = pack2(sqc[c]);
            #pragma unroll
            for (int i = 0; i < 4; ++i) {
                unsigned long long adj = add2(fma2g(neg2, acc[i][j], sqp[i]), scp);
                int f2   = (qg << 2) + i;
                int physs = f2 ^ cg;
                *(unsigned long long*)(dist + c * QT + (physs << 1)) = adj;
            }
        }
        __syncthreads();   // dist(chunk) ready; cT free

        // ---- phase 2: store cT(next) | sqc(next) | select(chunk)
        if (chunk + 1 < NN / CT) {
            #pragma unroll
            for (int it = 0; it < 4; ++it) {
                int f    = it * NTHREADS + tid;
                int c    = f >> 4;
                int k4g  = f & 15;
                int phys = (c >> 2) ^ k4g;
                int base = (k4g << 2) * CT + (phys << 2) + (c & 3);
                cT[base + 0 * CT] = pf[it].x;
                cT[base + 1 * CT] = pf[it].y;
                cT[base + 2 * CT] = pf[it].z;
                cT[base + 3 * CT] = pf[it].w;
            }
            if (tid >= 128 && tid < 128 + CT) {
                const float4* g4 = (const float4*)(ptsB + (size_t)(cbase + CT + tid - 128) * CC);
                float a[32];
                #pragma unroll
                for (int i = 0; i < 16; ++i) {
                    float4 v = g4[i];
                    a[2 * i]     = __fadd_rn(__fmul_rn(v.x, v.x), __fmul_rn(v.y, v.y));
                    a[2 * i + 1] = __fadd_rn(__fmul_rn(v.z, v.z), __fmul_rn(v.w, v.w));
                }
                #pragma unroll
                for (int off = 16; off >= 1; off >>= 1)
                    #pragma unroll
                    for (int l = 0; l < 16; ++l)
                        if (l < off) a[l] = __fadd_rn(a[l], a[l + off]);
                sqc[tid - 128] = a[0];
            }
        }

        if (tid < QT) {
            unsigned long long* row = topk + tid * KD;
            #pragma unroll 1
            for (int c8 = 0; c8 < CT; c8 += 8) {
                float av[8];
                #pragma unroll
                for (int u = 0; u < 8; ++u) {
                    int c = c8 + u;
                    int phys = (tid >> 1) ^ (c >> 2);
                    av[u] = dist[c * QT + (phys << 1) + (tid & 1)];
                }
                float m = fminf(fminf(fminf(av[0], av[1]), fminf(av[2], av[3])),
                                fminf(fminf(av[4], av[5]), fminf(av[6], av[7])));
                if (m > thr) continue;   // NaN thr -> enter (fills rows first)
                #pragma unroll
                for (int u = 0; u < 8; ++u) {
                    if (av[u] > thr) continue;
                    unsigned long long key =
                        ((unsigned long long)ord32(av[u]) << 32) |
                        (unsigned int)(cbase + c8 + u);
                    if (key < row[KD - 1]) {
                        int p = KD - 1;
                        while (p > 0 && row[p - 1] > key) { row[p] = row[p - 1]; --p; }
                        row[p] = key;
                        thr = iord32((unsigned int)(row[KD - 1] >> 32));
                    }
                }
            }
        }
        __syncthreads();
    }

    // ---- epilogue: gather xyz for even ranks (dilation 2)
    if (tid < QT) {
        int qglob = qbase + tid;
        const float* xb = xyz + ((size_t)b * NN + qglob) * 3;
        float x0 = xb[0], x1 = xb[1], x2 = xb[2];
        float* o = out + (((size_t)b * NN + qglob) * KOUT) * 10;
        const unsigned long long* row = topk + tid * KD;
        #pragma unroll 4
        for (int j = 0; j < KOUT; ++j) {
            unsigned int idx = (unsigned int)(row[2 * j] & 0xFFFFFFFFull);
            const float* nb = xyz + ((size_t)b * NN + idx) * 3;
            float n0 = nb[0], n1 = nb[1], n2 = nb[2];
            float r0 = x0 - n0, r1 = x1 - n1, r2 = x2 - n2;
            float d  = sqrtf(r0 * r0 + r1 * r1 + r2 * r2);
            float* oj = o + j * 10;
            oj[0] = d;
            oj[1] = r0; oj[2] = r1; oj[3] = r2;
            oj[4] = x0; oj[5] = x1; oj[6] = x2;
            oj[7] = n0; oj[8] = n1; oj[9] = n2;
        }
    }
}

extern "C" void kernel_launch(void* const* d_in, const int* in_sizes, int n_in,
                              void* d_out, int out_size) {
    const float* in0 = (const float*)d_in[0];
    const float* in1 = (const float*)d_in[1];
    const float* xyz;
    const float* pts;
    if (in_sizes[0] == BB * NN * 3) { xyz = in0; pts = in1; }
    else                            { xyz = in1; pts = in0; }

    cudaFuncSetAttribute(knn_pe_kernel,
                         cudaFuncAttributeMaxDynamicSharedMemorySize, SMEM_BYTES);

    dim3 grid(NN / QT, BB);
    knn_pe_kernel<<<grid, NTHREADS, SMEM_BYTES>>>(xyz, pts, (float*)d_out);
}

// round 4
// speedup vs baseline: 1.7332x; 1.7332x over previous
#include <cuda_runtime.h>

#define BB      8
#define NN      4096
#define CC      64
#define KD      32
#define KOUT    16
#define QT      128
#define CT      64
#define NC      (NN / CT)
#define NTHREADS 256

// smem floats: qT 8192 | cT 4096 | dist 8192 | sqc2 128 = 20608 f
// then topk 128*32 u64
#define SMEM_BYTES ((8192 + 4096 + 8192 + 128) * 4 + QT * KD * 8)   // 115200

__device__ float g_sqc[BB * NN];

__device__ __forceinline__ void fma2(unsigned long long& d,
                                     unsigned long long a,
                                     unsigned long long b) {
    asm("fma.rn.f32x2 %0, %1, %2, %0;" : "+l"(d) : "l"(a), "l"(b));
}
__device__ __forceinline__ unsigned long long pack2(float x) {
    unsigned long long r;
    asm("mov.b64 %0, {%1, %1};" : "=l"(r) : "f"(x));
    return r;
}
__device__ __forceinline__ unsigned int ord32(float f) {
    unsigned int b = __float_as_uint(f);
    return b ^ ((b & 0x80000000u) ? 0xFFFFFFFFu : 0x80000000u);
}
__device__ __forceinline__ float iord32(unsigned int y) {
    unsigned int b = (y & 0x80000000u) ? (y ^ 0x80000000u) : ~y;
    return __uint_as_float(b);
}
__device__ __forceinline__ void cpa16(void* smem_dst, const void* gsrc) {
    unsigned int s = (unsigned int)__cvta_generic_to_shared(smem_dst);
    asm volatile("cp.async.cg.shared.global [%0], [%1], 16;" :: "r"(s), "l"(gsrc));
}
#define CP_COMMIT() asm volatile("cp.async.commit_group;")
#define CP_WAIT0()  asm volatile("cp.async.wait_group 0;")

// ---- pre-kernel: exact XLA-order squared norms for all points ----
__global__ void __launch_bounds__(256) sqnorm_kernel(const float* __restrict__ pts) {
    int i = blockIdx.x * 256 + threadIdx.x;          // 0 .. BB*NN-1
    const float4* g4 = (const float4*)(pts + (size_t)i * CC);
    float a[32];
    #pragma unroll
    for (int t = 0; t < 16; ++t) {
        float4 v = g4[t];
        a[2 * t]     = __fadd_rn(__fmul_rn(v.x, v.x), __fmul_rn(v.y, v.y));
        a[2 * t + 1] = __fadd_rn(__fmul_rn(v.z, v.z), __fmul_rn(v.w, v.w));
    }
    #pragma unroll
    for (int off = 16; off >= 1; off >>= 1)
        #pragma unroll
        for (int l = 0; l < 16; ++l)
            if (l < off) a[l] = __fadd_rn(a[l], a[l + off]);
    g_sqc[i] = a[0];
}

__global__ void __launch_bounds__(NTHREADS, 2)
knn_pe_kernel(const float* __restrict__ xyz,   // [B,N,3]
              const float* __restrict__ pts,   // [B,N,64]
              float* __restrict__ out)         // [B,N,16,10]
{
    extern __shared__ float smem[];
    float* qT   = smem;                  // [64][128] k-major
    float* cT   = qT + 64 * QT;          // [64 cand][64 feat] row-major, k4^cg swizzled
    float* dist = cT + CT * CC;          // inner, c-major, f2-swizzled
    float* sqc2 = dist + CT * QT;        // [2][64] double-buffered candidate norms
    unsigned long long* topk = (unsigned long long*)(sqc2 + 128);

    const int tid   = threadIdx.x;
    const int b     = blockIdx.y;
    const int qbase = blockIdx.x * QT;
    const float* ptsB = pts + (size_t)b * NN * CC;
    const float* sqB  = g_sqc + b * NN;

    // ---- prologue: qT transpose + topk init + cp.async chunk 0
    {
        const float4* g = (const float4*)(ptsB + (size_t)qbase * CC);
        for (int f = tid; f < QT * (CC / 4); f += NTHREADS) {
            int row = f >> 4;
            int k4  = (f & 15) << 2;
            float4 v = g[f];
            qT[(k4 + 0) * QT + row] = v.x;
            qT[(k4 + 1) * QT + row] = v.y;
            qT[(k4 + 2) * QT + row] = v.z;
            qT[(k4 + 3) * QT + row] = v.w;
        }
    }
    for (int i = tid; i < QT * KD; i += NTHREADS)
        topk[i] = 0xFFFFFFFFFFFFFFFFull;

    float sqQ = (tid < QT) ? __ldg(sqB + qbase + tid) : 0.0f;

    // cp.async: candidate tile 0 (swizzled dst) + sqc buffer 0
    #pragma unroll
    for (int it = 0; it < 4; ++it) {
        int f  = it * NTHREADS + tid;
        int c  = f >> 4;
        int k4 = f & 15;
        cpa16(cT + c * CC + ((k4 ^ ((c >> 2) & 15)) << 2),
              ptsB + (size_t)c * CC + (k4 << 2));
    }
    if (tid < 16) cpa16(sqc2 + tid * 4, sqB + tid * 4);
    CP_COMMIT();
    CP_WAIT0();
    __syncthreads();

    const int qg = tid >> 4;   // 0..15 (8 queries each)
    const int cg = tid & 15;   // 0..15 (4 candidates each)
    float thr = iord32(0xFFFFFFFFu);   // NaN: slow path until rows fill

    for (int chunk = 0; chunk < NC; ++chunk) {
        const int cbase = chunk * CT;

        // ---- GEMM: inner[8q][4c] per thread, fma2 packs query pairs, k ascending
        unsigned long long acc[4][4];
        #pragma unroll
        for (int i = 0; i < 4; ++i)
            #pragma unroll
            for (int j = 0; j < 4; ++j) acc[i][j] = 0ull;

        #pragma unroll 2
        for (int k4 = 0; k4 < 16; ++k4) {
            float4 bv[4];
            #pragma unroll
            for (int j = 0; j < 4; ++j) {
                int c = (cg << 2) + j;
                bv[j] = *(const float4*)(cT + c * CC + ((k4 ^ cg) << 2));
            }
            #pragma unroll
            for (int m = 0; m < 4; ++m) {
                int k = (k4 << 2) + m;
                const float* qrow = qT + k * QT + (qg << 3);
                ulonglong2 aa = *(const ulonglong2*)(qrow);
                ulonglong2 ab = *(const ulonglong2*)(qrow + 4);
                float bs0 = (m == 0) ? bv[0].x : (m == 1) ? bv[0].y : (m == 2) ? bv[0].z : bv[0].w;
                float bs1 = (m == 0) ? bv[1].x : (m == 1) ? bv[1].y : (m == 2) ? bv[1].z : bv[1].w;
                float bs2 = (m == 0) ? bv[2].x : (m == 1) ? bv[2].y : (m == 2) ? bv[2].z : bv[2].w;
                float bs3 = (m == 0) ? bv[3].x : (m == 1) ? bv[3].y : (m == 2) ? bv[3].z : bv[3].w;
                unsigned long long b0 = pack2(bs0);
                unsigned long long b1 = pack2(bs1);
                unsigned long long b2 = pack2(bs2);
                unsigned long long b3 = pack2(bs3);
                fma2(acc[0][0], aa.x, b0); fma2(acc[0][1], aa.x, b1);
                fma2(acc[0][2], aa.x, b2); fma2(acc[0][3], aa.x, b3);
                fma2(acc[1][0], aa.y, b0); fma2(acc[1][1], aa.y, b1);
                fma2(acc[1][2], aa.y, b2); fma2(acc[1][3], aa.y, b3);
                fma2(acc[2][0], ab.x, b0); fma2(acc[2][1], ab.x, b1);
                fma2(acc[2][2], ab.x, b2); fma2(acc[2][3], ab.x, b3);
                fma2(acc[3][0], ab.y, b0); fma2(acc[3][1], ab.y, b1);
                fma2(acc[3][2], ab.y, b2); fma2(acc[3][3], ab.y, b3);
            }
        }

        // store inner pairs, c-major, f2-swizzled
        #pragma unroll
        for (int j = 0; j < 4; ++j) {
            int c = (cg << 2) + j;
            #pragma unroll
            for (int i = 0; i < 4; ++i) {
                int physs = ((qg << 2) + i) ^ cg;
                *(unsigned long long*)(dist + c * QT + (physs << 1)) = acc[i][j];
            }
        }
        __syncthreads();   // dist ready; cT consumed

        // ---- phase 2: cp.async next tile first, then selection overlaps it
        if (chunk + 1 < NC) {
            const float* src = ptsB + (size_t)(cbase + CT) * CC;
            #pragma unroll
            for (int it = 0; it < 4; ++it) {
                int f  = it * NTHREADS + tid;
                int c  = f >> 4;
                int k4 = f & 15;
                cpa16(cT + c * CC + ((k4 ^ ((c >> 2) & 15)) << 2),
                      src + (size_t)c * CC + (k4 << 2));
            }
            if (tid < 16)
                cpa16(sqc2 + ((chunk + 1) & 1) * 64 + tid * 4,
                      sqB + cbase + CT + tid * 4);
        }
        CP_COMMIT();

        if (tid < QT) {
            const float* sqcc = sqc2 + (chunk & 1) * 64;
            unsigned long long* row = topk + tid * KD;
            #pragma unroll 1
            for (int c8 = 0; c8 < CT; c8 += 8) {
                float av[8];
                #pragma unroll
                for (int u = 0; u < 8; ++u) {
                    int c = c8 + u;
                    int phys = (tid >> 1) ^ (c >> 2);
                    float inner = dist[c * QT + (phys << 1) + (tid & 1)];
                    av[u] = __fadd_rn(fmaf(-2.0f, inner, sqQ), sqcc[c]);
                }
                float mn = fminf(fminf(fminf(av[0], av[1]), fminf(av[2], av[3])),
                                 fminf(fminf(av[4], av[5]), fminf(av[6], av[7])));
                if (mn > thr) continue;   // NaN thr -> enter until rows fill
                #pragma unroll
                for (int u = 0; u < 8; ++u) {
                    if (av[u] > thr) continue;
                    unsigned long long key =
                        ((unsigned long long)ord32(av[u]) << 32) |
                        (unsigned int)(cbase + c8 + u);
                    if (key < row[KD - 1]) {
                        int p = KD - 1;
                        while (p > 0 && row[p - 1] > key) { row[p] = row[p - 1]; --p; }
                        row[p] = key;
                        thr = iord32((unsigned int)(row[KD - 1] >> 32));
                    }
                }
            }
        }
        CP_WAIT0();
        __syncthreads();   // cT(next), sqc(next) ready; dist free
    }

    // ---- epilogue: all 256 threads, 8 (query, j) pairs each
    const float* xyzB = xyz + (size_t)b * NN * 3;
    #pragma unroll 2
    for (int p = 0; p < 8; ++p) {
        int pair = p * NTHREADS + tid;     // 0..2047
        int q = pair >> 4;
        int j = pair & 15;
        unsigned int idx =
            (unsigned int)(topk[q * KD + 2 * j] & 0xFFFFFFFFull);
        const float* xb = xyzB + (size_t)(qbase + q) * 3;
        const float* nb = xyzB + (size_t)idx * 3;
        float x0 = xb[0], x1 = xb[1], x2 = xb[2];
        float n0 = nb[0], n1 = nb[1], n2 = nb[2];
        float r0 = x0 - n0, r1 = x1 - n1, r2 = x2 - n2;
        float d  = sqrtf(r0 * r0 + r1 * r1 + r2 * r2);
        float* oj = out + ((((size_t)b * NN + qbase + q) * KOUT) + j) * 10;
        oj[0] = d;
        oj[1] = r0; oj[2] = r1; oj[3] = r2;
        oj[4] = x0; oj[5] = x1; oj[6] = x2;
        oj[7] = n0; oj[8] = n1; oj[9] = n2;
    }
}

extern "C" void kernel_launch(void* const* d_in, const int* in_sizes, int n_in,
                              void* d_out, int out_size) {
    const float* in0 = (const float*)d_in[0];
    const float* in1 = (const float*)d_in[1];
    const float* xyz;
    const float* pts;
    if (in_sizes[0] == BB * NN * 3) { xyz = in0; pts = in1; }
    else                            { xyz = in1; pts = in0; }

    cudaFuncSetAttribute(knn_pe_kernel,
                         cudaFuncAttributeMaxDynamicSharedMemorySize, SMEM_BYTES);

    sqnorm_kernel<<<BB * NN / 256, 256>>>(pts);
    dim3 grid(NN / QT, BB);
    knn_pe_kernel<<<grid, NTHREADS, SMEM_BYTES>>>(xyz, pts, (float*)d_out);
}